// round 3
// baseline (speedup 1.0000x reference)
#include <cuda_runtime.h>
#include <math.h>

#define HWX 262144   // 512*512
#define NCH 64
#define KS  576

// Scratch (__device__ globals; no allocation allowed)
__device__ float g_part[NCH * 16 * 9];  // per-channel, per-block-x window maxima
__device__ float g_rk[NCH * 12];        // padded: rk[c*12+t] = 1/(scale_{c,t} * s_qx), t<9
__device__ float g_sqx;                 // x fake-quant step

// ---------------------------------------------------------------------------
// Kernel 1: per-channel windowed abs-max -> partials (no atomics, no init).
// Window (kh,kw): excludes input row 511 if kh==0, row 0 if kh==2 (cols symm).
// ---------------------------------------------------------------------------
__global__ __launch_bounds__(256) void actmax_kernel(const float* __restrict__ in) {
    int ch = blockIdx.y;
    const float4* p = reinterpret_cast<const float4*>(in + (size_t)ch * HWX);

    float m[9];
#pragma unroll
    for (int i = 0; i < 9; i++) m[i] = 0.f;
    float mi = 0.f;  // interior max (subset of every window)

    for (int i = blockIdx.x * blockDim.x + threadIdx.x; i < HWX / 4;
         i += gridDim.x * blockDim.x) {
        float4 v = p[i];
        float a0 = fabsf(v.x), a1 = fabsf(v.y), a2 = fabsf(v.z), a3 = fabsf(v.w);
        int e  = i << 2;
        int r  = e >> 9;
        int c0 = e & 511;
        if (r != 0 && r != 511 && c0 != 0 && c0 != 508) {
            mi = fmaxf(mi, fmaxf(fmaxf(a0, a1), fmaxf(a2, a3)));
        } else {
            bool r0 = (r != 511), r2 = (r != 0);
            float a[4] = {a0, a1, a2, a3};
#pragma unroll
            for (int j = 0; j < 4; j++) {
                int  c  = c0 + j;
                bool w0 = (c != 511), w2 = (c != 0);
                float av = a[j];
                m[0] = fmaxf(m[0], (r0 && w0) ? av : 0.f);
                m[1] = fmaxf(m[1],  r0        ? av : 0.f);
                m[2] = fmaxf(m[2], (r0 && w2) ? av : 0.f);
                m[3] = fmaxf(m[3],  w0        ? av : 0.f);
                m[4] = fmaxf(m[4],  av);
                m[5] = fmaxf(m[5],  w2        ? av : 0.f);
                m[6] = fmaxf(m[6], (r2 && w0) ? av : 0.f);
                m[7] = fmaxf(m[7],  r2        ? av : 0.f);
                m[8] = fmaxf(m[8], (r2 && w2) ? av : 0.f);
            }
        }
    }
#pragma unroll
    for (int i = 0; i < 9; i++) m[i] = fmaxf(m[i], mi);

    // warp reduce (values >= 0 -> uint order == float order)
#pragma unroll
    for (int off = 16; off; off >>= 1) {
#pragma unroll
        for (int i = 0; i < 9; i++)
            m[i] = fmaxf(m[i], __shfl_xor_sync(0xffffffffu, m[i], off));
    }

    __shared__ unsigned sm[9];
    if (threadIdx.x < 9) sm[threadIdx.x] = 0u;
    __syncthreads();
    if ((threadIdx.x & 31) == 0) {
#pragma unroll
        for (int i = 0; i < 9; i++) atomicMax(&sm[i], __float_as_uint(m[i]));
    }
    __syncthreads();
    if (threadIdx.x < 9)
        g_part[ch * 144 + blockIdx.x * 9 + threadIdx.x] =
            __uint_as_float(sm[threadIdx.x]);
}

// ---------------------------------------------------------------------------
// Kernel 2: reduce partials, compute scales/quant steps, emit wq (one block).
// ---------------------------------------------------------------------------
__global__ __launch_bounds__(576) void scale_kernel(const float* __restrict__ w,
                                                    float* __restrict__ out) {
    __shared__ float red_ax[18], red_wx[18];
    __shared__ float s_q[2];

    int k = threadIdx.x;               // 0..575 = c*9 + t
    int c = k / 9, t = k % 9;

    float act = 0.f;
#pragma unroll
    for (int b = 0; b < 16; b++) act = fmaxf(act, g_part[c * 144 + b * 9 + t]);

    float wm = 0.f;
#pragma unroll 8
    for (int co = 0; co < 64; ++co) wm = fmaxf(wm, fabsf(w[co * KS + k]));

    float sc = sqrtf(act) / sqrtf(wm);
    if (sc == 0.f) sc = 1.f;

    float ax = act / sc;   // column amax of x/scale
    float wx = wm * sc;    // column amax of w*scale

#pragma unroll
    for (int off = 16; off; off >>= 1) {
        ax = fmaxf(ax, __shfl_xor_sync(0xffffffffu, ax, off));
        wx = fmaxf(wx, __shfl_xor_sync(0xffffffffu, wx, off));
    }
    if ((k & 31) == 0) { red_ax[k >> 5] = ax; red_wx[k >> 5] = wx; }
    __syncthreads();
    if (k == 0) {
        float a = 0.f, b = 0.f;
        for (int i = 0; i < 18; i++) { a = fmaxf(a, red_ax[i]); b = fmaxf(b, red_wx[i]); }
        s_q[0] = (a > 0.f) ? a / 127.f : 1.f;   // s_qx
        s_q[1] = (b > 0.f) ? b / 127.f : 1.f;   // s_qw
        g_sqx  = s_q[0];
    }
    __syncthreads();
    float sqx = s_q[0], sqw = s_q[1];
    float rqw = 1.0f / sqw;

    g_rk[c * 12 + t] = 1.0f / (sc * sqx);

    // wq output: (Cout, K, K, C) at start of out
    int kh = t / 3, kw = t % 3;
    int ob = kh * 192 + kw * 64 + c;
#pragma unroll 8
    for (int co = 0; co < 64; ++co) {
        float u = (w[co * KS + k] * sc) * rqw;
        u = fminf(fmaxf(u, -127.f), 127.f);
        out[co * KS + ob] = rintf(u) * sqw;
    }
}

// ---------------------------------------------------------------------------
// Kernel 3: fused 9-tap quantize-fold + NCHW->NHWC transpose, all-128-bit.
// Block = 1 h-row x 64 w x 64 c. Thread = 4 channels x 4 w register subtile.
// Smem transpose tile[64][64] with XOR swizzle (colgrp ^ (row>>2)) -> both
// STS.128 and LDS.128 phases bank-conflict-free.
// ---------------------------------------------------------------------------
__global__ __launch_bounds__(256) void main_kernel(const float* __restrict__ in,
                                                   float* __restrict__ out) {
    __shared__ float srk[NCH * 12];
    __shared__ float tile[64 * 64];

    int tid = threadIdx.x;
    for (int i = tid; i < NCH * 12; i += 256) srk[i] = g_rk[i];
    float sq = g_sqx;

    int h    = blockIdx.y;
    int wblk = blockIdx.x * 64;
    float rm0 = (h != 511) ? 1.f : 0.f;   // kh=0 row valid
    float rm2 = (h != 0)   ? 1.f : 0.f;   // kh=2 row valid

    int w4   = tid & 15;          // which group of 4 w
    int cbg  = tid >> 4;          // which group of 4 channels
    int cb   = cbg * 4;
    int wloc = w4 * 4;

    float cm0[4], cm2[4];
#pragma unroll
    for (int j = 0; j < 4; j++) {
        int gw = wblk + wloc + j;
        cm0[j] = (gw != 511) ? 1.f : 0.f;  // kw=0 valid
        cm2[j] = (gw != 0)   ? 1.f : 0.f;  // kw=2 valid
    }
    __syncthreads();

    float a[4][4];
    size_t base = (size_t)h * 512 + wblk + wloc;
#pragma unroll
    for (int i = 0; i < 4; i++) {
        int c = cb + i;
        float4 v  = *reinterpret_cast<const float4*>(in + (size_t)c * HWX + base);
        float4 k0 = *reinterpret_cast<const float4*>(&srk[c * 12]);
        float4 k1 = *reinterpret_cast<const float4*>(&srk[c * 12 + 4]);
        float4 k2 = *reinterpret_cast<const float4*>(&srk[c * 12 + 8]);
        float vv[4] = {v.x, v.y, v.z, v.w};
#pragma unroll
        for (int j = 0; j < 4; j++) {
            float x  = vv[j];
            float r0 = rintf(x * k0.x), r1 = rintf(x * k0.y), r2 = rintf(x * k0.z);
            float r3 = rintf(x * k0.w), r4 = rintf(x * k1.x), r5 = rintf(x * k1.y);
            float r6 = rintf(x * k1.z), r7 = rintf(x * k1.w), r8 = rintf(x * k2.x);
            float row0 = fmaf(r2, cm2[j], fmaf(r0, cm0[j], r1));
            float row1 = fmaf(r5, cm2[j], fmaf(r3, cm0[j], r4));
            float row2 = fmaf(r8, cm2[j], fmaf(r6, cm0[j], r7));
            a[i][j] = sq * fmaf(row0, rm0, fmaf(row2, rm2, row1));
        }
    }

    // register transpose -> smem, w-major rows, swizzled channel groups
#pragma unroll
    for (int j = 0; j < 4; j++) {
        int row = wloc + j;                       // row>>2 == w4
        int col = (cbg ^ w4) << 2;
        *reinterpret_cast<float4*>(&tile[row * 64 + col]) =
            make_float4(a[0][j], a[1][j], a[2][j], a[3][j]);
    }
    __syncthreads();

    // phase 2: coalesced NHWC store
    int cg = tid & 15;
    int wr = tid >> 4;
    float* ob = out + 36864 + ((size_t)h * 512 + wblk) * 64;
#pragma unroll
    for (int jj = 0; jj < 4; jj++) {
        int w = wr + 16 * jj;
        float4 t4 = *reinterpret_cast<const float4*>(
            &tile[w * 64 + ((cg ^ (w >> 2)) << 2)]);
        *reinterpret_cast<float4*>(&ob[(size_t)w * 64 + cg * 4]) = t4;
    }
}

// ---------------------------------------------------------------------------
extern "C" void kernel_launch(void* const* d_in, const int* in_sizes, int n_in,
                              void* d_out, int out_size) {
    const float* in;
    const float* w;
    if (in_sizes[0] == 64 * 512 * 512) { in = (const float*)d_in[0]; w = (const float*)d_in[1]; }
    else                               { in = (const float*)d_in[1]; w = (const float*)d_in[0]; }
    float* out = (float*)d_out;

    dim3 g1(16, 64);
    actmax_kernel<<<g1, 256>>>(in);
    scale_kernel<<<1, 576>>>(w, out);
    dim3 g3(8, 512);
    main_kernel<<<g3, 256>>>(in, out);
}

// round 4
// speedup vs baseline: 1.2166x; 1.2166x over previous
#include <cuda_runtime.h>
#include <math.h>

#define HWX 262144   // 512*512
#define NCH 64
#define KS  576
#define RMAGIC 12582912.0f   // 1.5*2^23 : round-to-nearest-even shifter

// Scratch (__device__ globals; no allocation allowed)
__device__ float g_part[NCH * 64 * 9];  // per (channel, row-group) window maxima
__device__ float g_rk[NCH * 12];        // padded: rk[c*12+t] = 1/(scale_{c,t} * s_qx)
__device__ float g_sqx;                 // x fake-quant step

// ---------------------------------------------------------------------------
// Kernel 1: per-channel windowed abs-max.
// Block = (channel, group of 8 rows); 256 threads, 4 float4 each, unrolled.
// Col edges (0, 511) are thread-uniform (t%128==0 / ==127); row edges (0, 511)
// are (k, t-half)-uniform in blocks rg==0 / rg==63. Interior threads do pure
// LDG.128 + fabs/fmax — no per-element index math.
// ---------------------------------------------------------------------------
__global__ __launch_bounds__(256) void actmax_kernel(const float* __restrict__ in) {
    int ch = blockIdx.y;
    int rg = blockIdx.x;  // 0..63
    const float4* p = reinterpret_cast<const float4*>(in)
                    + (size_t)ch * 65536 + (size_t)rg * 1024;
    int t = threadIdx.x;
    int lanepos = t & 127;                 // float4 position within its row
    bool isC0 = (lanepos == 0), isC511 = (lanepos == 127);

    float mm = 0.f, sm = 0.f;              // mid-col max: normal rows / special row
    float mc0 = 0.f, sc0 = 0.f, mc511 = 0.f, sc511 = 0.f;

#pragma unroll
    for (int k = 0; k < 4; k++) {
        float4 v = p[t + 256 * k];
        bool sp = (rg == 0)  ? (k == 0 && t < 128)
                : (rg == 63) ? (k == 3 && t >= 128) : false;
        float a0 = fabsf(v.x), a1 = fabsf(v.y), a2 = fabsf(v.z), a3 = fabsf(v.w);
        float m3;
        if (isC0) {
            m3 = fmaxf(fmaxf(a1, a2), a3);
            if (sp) sc0 = fmaxf(sc0, a0); else mc0 = fmaxf(mc0, a0);
        } else if (isC511) {
            m3 = fmaxf(fmaxf(a0, a1), a2);
            if (sp) sc511 = fmaxf(sc511, a3); else mc511 = fmaxf(mc511, a3);
        } else {
            m3 = fmaxf(fmaxf(a0, a1), fmaxf(a2, a3));
        }
        if (sp) sm = fmaxf(sm, m3); else mm = fmaxf(mm, m3);
    }

#pragma unroll
    for (int off = 16; off; off >>= 1) {
        mm = fmaxf(mm, __shfl_xor_sync(0xffffffffu, mm, off));
        sm = fmaxf(sm, __shfl_xor_sync(0xffffffffu, sm, off));
    }

    __shared__ float swm[8], sws[8];
    __shared__ float e_mc0[2], e_sc0[2], e_mc511[2], e_sc511[2];
    int wid = t >> 5;
    if ((t & 31) == 0) { swm[wid] = mm; sws[wid] = sm; }
    if (isC0)   { e_mc0[t >> 7] = mc0;     e_sc0[t >> 7] = sc0; }
    if (isC511) { e_mc511[t >> 7] = mc511; e_sc511[t >> 7] = sc511; }
    __syncthreads();

    if (t == 0) {
        float Rm = 0.f, Sm = 0.f;
#pragma unroll
        for (int i = 0; i < 8; i++) { Rm = fmaxf(Rm, swm[i]); Sm = fmaxf(Sm, sws[i]); }
        float Rc0   = fmaxf(e_mc0[0], e_mc0[1]),     Sc0   = fmaxf(e_sc0[0], e_sc0[1]);
        float Rc511 = fmaxf(e_mc511[0], e_mc511[1]), Sc511 = fmaxf(e_sc511[0], e_sc511[1]);
        // per-kw maxima: C(0)=cols 0..510, C(1)=all, C(2)=cols 1..511
        float r9[3] = { fmaxf(Rc0, Rm), fmaxf(fmaxf(Rc0, Rc511), Rm), fmaxf(Rm, Rc511) };
        float s9[3] = { fmaxf(Sc0, Sm), fmaxf(fmaxf(Sc0, Sc511), Sm), fmaxf(Sm, Sc511) };
        int excl = (rg == 0) ? 2 : (rg == 63) ? 0 : -1;  // kh excluding the special row
        float* dst = &g_part[((size_t)ch * 64 + rg) * 9];
#pragma unroll
        for (int kh = 0; kh < 3; kh++)
#pragma unroll
            for (int kw = 0; kw < 3; kw++)
                dst[kh * 3 + kw] = (kh == excl) ? r9[kw] : fmaxf(r9[kw], s9[kw]);
    }
}

// ---------------------------------------------------------------------------
// Kernel 2: reduce partials, compute scales/quant steps, emit wq (one block).
// ---------------------------------------------------------------------------
__global__ __launch_bounds__(576) void scale_kernel(const float* __restrict__ w,
                                                    float* __restrict__ out) {
    __shared__ float red_ax[18], red_wx[18];
    __shared__ float s_q[2];

    int k = threadIdx.x;               // 0..575 = c*9 + t
    int c = k / 9, t = k % 9;

    float act = 0.f;
#pragma unroll 8
    for (int b = 0; b < 64; b++)
        act = fmaxf(act, g_part[((size_t)c * 64 + b) * 9 + t]);

    float wm = 0.f;
#pragma unroll 8
    for (int co = 0; co < 64; ++co) wm = fmaxf(wm, fabsf(w[co * KS + k]));

    float sc = sqrtf(act) / sqrtf(wm);
    if (sc == 0.f) sc = 1.f;

    float ax = act / sc;   // column amax of x/scale
    float wx = wm * sc;    // column amax of w*scale

#pragma unroll
    for (int off = 16; off; off >>= 1) {
        ax = fmaxf(ax, __shfl_xor_sync(0xffffffffu, ax, off));
        wx = fmaxf(wx, __shfl_xor_sync(0xffffffffu, wx, off));
    }
    if ((k & 31) == 0) { red_ax[k >> 5] = ax; red_wx[k >> 5] = wx; }
    __syncthreads();
    if (k == 0) {
        float a = 0.f, b = 0.f;
        for (int i = 0; i < 18; i++) { a = fmaxf(a, red_ax[i]); b = fmaxf(b, red_wx[i]); }
        s_q[0] = (a > 0.f) ? a / 127.f : 1.f;   // s_qx
        s_q[1] = (b > 0.f) ? b / 127.f : 1.f;   // s_qw
        g_sqx  = s_q[0];
    }
    __syncthreads();
    float sqx = s_q[0], sqw = s_q[1];
    float rqw = 1.0f / sqw;

    g_rk[c * 12 + t] = 1.0f / (sc * sqx);

    // wq output: (Cout, K, K, C) at start of out
    int kh = t / 3, kw = t % 3;
    int ob = kh * 192 + kw * 64 + c;
#pragma unroll 8
    for (int co = 0; co < 64; ++co) {
        float u = (w[co * KS + k] * sc) * rqw;
        u = fminf(fmaxf(u, -127.f), 127.f);
        out[co * KS + ob] = rintf(u) * sqw;
    }
}

// ---------------------------------------------------------------------------
// Kernel 3: fused 9-tap quantize-fold + NCHW->NHWC transpose, all-128-bit.
// rint via magic-number add/sub: fma(x,k,M)-M  (exact round-half-even for
// |x*k| <= 127), keeping all rounding work on the rt=2 fma pipe (no FRND).
// ---------------------------------------------------------------------------
__global__ __launch_bounds__(256) void main_kernel(const float* __restrict__ in,
                                                   float* __restrict__ out) {
    __shared__ float srk[NCH * 12];
    __shared__ float tile[64 * 64];

    int tid = threadIdx.x;
    for (int i = tid; i < NCH * 12; i += 256) srk[i] = g_rk[i];
    float sq = g_sqx;

    int h    = blockIdx.y;
    int wblk = blockIdx.x * 64;
    float rm0 = (h != 511) ? 1.f : 0.f;   // kh=0 row valid
    float rm2 = (h != 0)   ? 1.f : 0.f;   // kh=2 row valid

    int w4   = tid & 15;          // group of 4 w
    int cbg  = tid >> 4;          // group of 4 channels
    int cb   = cbg * 4;
    int wloc = w4 * 4;

    float cm0[4], cm2[4];
#pragma unroll
    for (int j = 0; j < 4; j++) {
        int gw = wblk + wloc + j;
        cm0[j] = (gw != 511) ? 1.f : 0.f;  // kw=0 valid
        cm2[j] = (gw != 0)   ? 1.f : 0.f;  // kw=2 valid
    }
    __syncthreads();

    float a[4][4];
    size_t base = (size_t)h * 512 + wblk + wloc;
#pragma unroll
    for (int i = 0; i < 4; i++) {
        int c = cb + i;
        float4 v  = *reinterpret_cast<const float4*>(in + (size_t)c * HWX + base);
        float4 k0 = *reinterpret_cast<const float4*>(&srk[c * 12]);
        float4 k1 = *reinterpret_cast<const float4*>(&srk[c * 12 + 4]);
        float4 k2 = *reinterpret_cast<const float4*>(&srk[c * 12 + 8]);
        float vv[4] = {v.x, v.y, v.z, v.w};
#pragma unroll
        for (int j = 0; j < 4; j++) {
            float x = vv[j];
            float r0 = __fadd_rn(__fmaf_rn(x, k0.x, RMAGIC), -RMAGIC);
            float r1 = __fadd_rn(__fmaf_rn(x, k0.y, RMAGIC), -RMAGIC);
            float r2 = __fadd_rn(__fmaf_rn(x, k0.z, RMAGIC), -RMAGIC);
            float r3 = __fadd_rn(__fmaf_rn(x, k0.w, RMAGIC), -RMAGIC);
            float r4 = __fadd_rn(__fmaf_rn(x, k1.x, RMAGIC), -RMAGIC);
            float r5 = __fadd_rn(__fmaf_rn(x, k1.y, RMAGIC), -RMAGIC);
            float r6 = __fadd_rn(__fmaf_rn(x, k1.z, RMAGIC), -RMAGIC);
            float r7 = __fadd_rn(__fmaf_rn(x, k1.w, RMAGIC), -RMAGIC);
            float r8 = __fadd_rn(__fmaf_rn(x, k2.x, RMAGIC), -RMAGIC);
            float row0 = fmaf(r2, cm2[j], fmaf(r0, cm0[j], r1));
            float row1 = fmaf(r5, cm2[j], fmaf(r3, cm0[j], r4));
            float row2 = fmaf(r8, cm2[j], fmaf(r6, cm0[j], r7));
            a[i][j] = sq * fmaf(row0, rm0, fmaf(row2, rm2, row1));
        }
    }

    // register transpose -> smem; XOR swizzle conflict-free per 8-lane phase
#pragma unroll
    for (int j = 0; j < 4; j++) {
        int row = wloc + j;                       // row>>2 == w4
        int col = (cbg ^ w4) << 2;
        *reinterpret_cast<float4*>(&tile[row * 64 + col]) =
            make_float4(a[0][j], a[1][j], a[2][j], a[3][j]);
    }
    __syncthreads();

    // phase 2: coalesced NHWC store
    int cg = tid & 15;
    int wr = tid >> 4;
    float* ob = out + 36864 + ((size_t)h * 512 + wblk) * 64;
#pragma unroll
    for (int jj = 0; jj < 4; jj++) {
        int w = wr + 16 * jj;
        float4 t4 = *reinterpret_cast<const float4*>(
            &tile[w * 64 + ((cg ^ (w >> 2)) << 2)]);
        *reinterpret_cast<float4*>(&ob[(size_t)w * 64 + cg * 4]) = t4;
    }
}

// ---------------------------------------------------------------------------
extern "C" void kernel_launch(void* const* d_in, const int* in_sizes, int n_in,
                              void* d_out, int out_size) {
    const float* in;
    const float* w;
    if (in_sizes[0] == 64 * 512 * 512) { in = (const float*)d_in[0]; w = (const float*)d_in[1]; }
    else                               { in = (const float*)d_in[1]; w = (const float*)d_in[0]; }
    float* out = (float*)d_out;

    dim3 g1(64, 64);
    actmax_kernel<<<g1, 256>>>(in);
    scale_kernel<<<1, 576>>>(w, out);
    dim3 g3(8, 512);
    main_kernel<<<g3, 256>>>(in, out);
}

// round 5
// speedup vs baseline: 1.3168x; 1.0823x over previous
#include <cuda_runtime.h>
#include <math.h>

#define HWX 262144   // 512*512
#define NCH 64
#define KS  576
#define RMAGIC 12582912.0f   // 1.5*2^23 round-to-nearest-even shifter

typedef unsigned long long ull;

// Scratch (__device__ globals; no allocation allowed)
__device__ float g_part[NCH * 8 * 9];   // per (channel, row-group) window maxima
__device__ float g_wm[KS];              // per-column weight abs-max
__device__ float g_sc[KS];              // smoothquant scale per column
__device__ float g_rk2[NCH * 20];      // duplicated: (k0,k0,k1,k1,...,k8,k8,pad,pad)
__device__ float g_sqx, g_sqw, g_rqw;

// ---- packed f32x2 helpers -------------------------------------------------
__device__ __forceinline__ ull pk2(float lo, float hi) {
    ull r; asm("mov.b64 %0, {%1, %2};" : "=l"(r) : "f"(lo), "f"(hi)); return r;
}
__device__ __forceinline__ void upk2(ull v, float& lo, float& hi) {
    asm("mov.b64 {%0, %1}, %2;" : "=f"(lo), "=f"(hi) : "l"(v));
}
__device__ __forceinline__ ull f2fma(ull a, ull b, ull c) {
    ull d; asm("fma.rn.f32x2 %0, %1, %2, %3;" : "=l"(d) : "l"(a), "l"(b), "l"(c)); return d;
}
__device__ __forceinline__ ull f2add(ull a, ull b) {
    ull d; asm("add.rn.f32x2 %0, %1, %2;" : "=l"(d) : "l"(a), "l"(b)); return d;
}
__device__ __forceinline__ ull f2mul(ull a, ull b) {
    ull d; asm("mul.rn.f32x2 %0, %1, %2;" : "=l"(d) : "l"(a), "l"(b)); return d;
}

// ---------------------------------------------------------------------------
// Kernel 1: grid (9, 64). blockIdx.x<8: per-channel windowed abs-max over a
// 64-row group (32 float4 per thread). blockIdx.x==8: per-column weight
// abs-max for channel blockIdx.y (runs concurrently, independent data).
// ---------------------------------------------------------------------------
template <int MODE>  // 0 = interior rows, 1 = contains row 0, 2 = contains row 511
__device__ __forceinline__ void actmax_loop(const float4* p, int t,
                                            bool isC0, bool isC511,
                                            float& mm, float& sm,
                                            float& mc0, float& sc0,
                                            float& mc511, float& sc511) {
#pragma unroll
    for (int k = 0; k < 32; k++) {
        float4 v = p[t + 256 * k];
        bool sp = (MODE == 1) ? (k == 0 && t < 128)
                : (MODE == 2) ? (k == 31 && t >= 128) : false;
        float m3;
        if (isC0) {
            m3 = fmaxf(fmaxf(fabsf(v.y), fabsf(v.z)), fabsf(v.w));
            float a = fabsf(v.x);
            if (sp) sc0 = fmaxf(sc0, a); else mc0 = fmaxf(mc0, a);
        } else if (isC511) {
            m3 = fmaxf(fmaxf(fabsf(v.x), fabsf(v.y)), fabsf(v.z));
            float a = fabsf(v.w);
            if (sp) sc511 = fmaxf(sc511, a); else mc511 = fmaxf(mc511, a);
        } else {
            m3 = fmaxf(fmaxf(fabsf(v.x), fabsf(v.y)), fmaxf(fabsf(v.z), fabsf(v.w)));
        }
        if (MODE != 0 && sp) sm = fmaxf(sm, m3); else mm = fmaxf(mm, m3);
    }
}

__global__ __launch_bounds__(256) void actmax_kernel(const float* __restrict__ in,
                                                     const float* __restrict__ w) {
    int ch = blockIdx.y;
    int t  = threadIdx.x;

    __shared__ float swm[8], sws[8];
    __shared__ float e_mc0[2], e_sc0[2], e_mc511[2], e_sc511[2];
    __shared__ float wred[2][9];

    if (blockIdx.x == 8) {
        // ---- weight abs-max for this channel's 9 columns ----
        float wv[9];
        if (t < 64) {
#pragma unroll
            for (int j = 0; j < 9; j++) wv[j] = fabsf(w[t * KS + ch * 9 + j]);
#pragma unroll
            for (int off = 16; off; off >>= 1)
#pragma unroll
                for (int j = 0; j < 9; j++)
                    wv[j] = fmaxf(wv[j], __shfl_xor_sync(0xffffffffu, wv[j], off));
            if ((t & 31) == 0)
#pragma unroll
                for (int j = 0; j < 9; j++) wred[t >> 5][j] = wv[j];
        }
        __syncthreads();
        if (t < 9) g_wm[ch * 9 + t] = fmaxf(wred[0][t], wred[1][t]);
        return;
    }

    int rg = blockIdx.x;  // 0..7, 64 rows each
    const float4* p = reinterpret_cast<const float4*>(in)
                    + (size_t)ch * 65536 + (size_t)rg * 8192;
    int lanepos = t & 127;
    bool isC0 = (lanepos == 0), isC511 = (lanepos == 127);

    float mm = 0.f, sm = 0.f, mc0 = 0.f, sc0 = 0.f, mc511 = 0.f, sc511 = 0.f;
    if (rg == 0)      actmax_loop<1>(p, t, isC0, isC511, mm, sm, mc0, sc0, mc511, sc511);
    else if (rg == 7) actmax_loop<2>(p, t, isC0, isC511, mm, sm, mc0, sc0, mc511, sc511);
    else              actmax_loop<0>(p, t, isC0, isC511, mm, sm, mc0, sc0, mc511, sc511);

#pragma unroll
    for (int off = 16; off; off >>= 1) {
        mm = fmaxf(mm, __shfl_xor_sync(0xffffffffu, mm, off));
        sm = fmaxf(sm, __shfl_xor_sync(0xffffffffu, sm, off));
    }
    if ((t & 31) == 0) { swm[t >> 5] = mm; sws[t >> 5] = sm; }
    if (isC0)   { e_mc0[t >> 7] = mc0;     e_sc0[t >> 7] = sc0; }
    if (isC511) { e_mc511[t >> 7] = mc511; e_sc511[t >> 7] = sc511; }
    __syncthreads();

    if (t == 0) {
        float Rm = 0.f, Sm = 0.f;
#pragma unroll
        for (int i = 0; i < 8; i++) { Rm = fmaxf(Rm, swm[i]); Sm = fmaxf(Sm, sws[i]); }
        float Rc0   = fmaxf(e_mc0[0], e_mc0[1]),     Sc0   = fmaxf(e_sc0[0], e_sc0[1]);
        float Rc511 = fmaxf(e_mc511[0], e_mc511[1]), Sc511 = fmaxf(e_sc511[0], e_sc511[1]);
        float r9[3] = { fmaxf(Rc0, Rm), fmaxf(fmaxf(Rc0, Rc511), Rm), fmaxf(Rm, Rc511) };
        float s9[3] = { fmaxf(Sc0, Sm), fmaxf(fmaxf(Sc0, Sc511), Sm), fmaxf(Sm, Sc511) };
        int excl = (rg == 0) ? 2 : (rg == 7) ? 0 : -1;
        float* dst = &g_part[((size_t)ch * 8 + rg) * 9];
#pragma unroll
        for (int kh = 0; kh < 3; kh++)
#pragma unroll
            for (int kw = 0; kw < 3; kw++)
                dst[kh * 3 + kw] = (kh == excl) ? r9[kw] : fmaxf(r9[kw], s9[kw]);
    }
}

// ---------------------------------------------------------------------------
// Kernel 2: scales + quant steps (one small block).
// ---------------------------------------------------------------------------
__global__ __launch_bounds__(576) void scale_kernel() {
    __shared__ float red_ax[18], red_wx[18];
    __shared__ float s_q[2];

    int k = threadIdx.x;  // c*9 + t
    int c = k / 9, t = k % 9;

    float act = 0.f;
#pragma unroll
    for (int b = 0; b < 8; b++)
        act = fmaxf(act, g_part[((size_t)c * 8 + b) * 9 + t]);
    float wm = g_wm[k];

    float sc = sqrtf(act) / sqrtf(wm);
    if (sc == 0.f) sc = 1.f;

    float ax = act / sc;
    float wx = wm * sc;
#pragma unroll
    for (int off = 16; off; off >>= 1) {
        ax = fmaxf(ax, __shfl_xor_sync(0xffffffffu, ax, off));
        wx = fmaxf(wx, __shfl_xor_sync(0xffffffffu, wx, off));
    }
    if ((k & 31) == 0) { red_ax[k >> 5] = ax; red_wx[k >> 5] = wx; }
    __syncthreads();
    if (k == 0) {
        float a = 0.f, b = 0.f;
        for (int i = 0; i < 18; i++) { a = fmaxf(a, red_ax[i]); b = fmaxf(b, red_wx[i]); }
        s_q[0] = (a > 0.f) ? a / 127.f : 1.f;
        s_q[1] = (b > 0.f) ? b / 127.f : 1.f;
        g_sqx = s_q[0]; g_sqw = s_q[1]; g_rqw = 1.0f / s_q[1];
    }
    __syncthreads();
    float sqx = s_q[0];

    g_sc[k] = sc;
    float rk = 1.0f / (sc * sqx);
    g_rk2[c * 20 + 2 * t]     = rk;
    g_rk2[c * 20 + 2 * t + 1] = rk;
}

// ---------------------------------------------------------------------------
// Kernel 2b: wq output, one block per cout. (Cout, K, K, C) at start of out.
// ---------------------------------------------------------------------------
__global__ __launch_bounds__(576) void wq_kernel(const float* __restrict__ w,
                                                 float* __restrict__ out) {
    int co = blockIdx.x;
    int k  = threadIdx.x;
    int c = k / 9, t = k % 9, kh = t / 3, kw = t % 3;
    float u = (w[co * KS + k] * g_sc[k]) * g_rqw;
    u = fminf(fmaxf(u, -127.f), 127.f);
    out[co * KS + kh * 192 + kw * 64 + c] = rintf(u) * g_sqw;
}

// ---------------------------------------------------------------------------
// Kernel 3: fused 9-tap quantize-fold + NCHW->NHWC transpose.
// All memory 128-bit; all math packed f32x2 (2 pixels/instr on the fma pipe).
// Per packed lane-pair: Y_t = fma2(X,K_t,M); R_t = add2(Y_t,-M) (exact int
// round-half-even); acc = fma2(R_t, MSK_t, acc) with MSK folding sq and the
// kw/kh border validity masks.
// ---------------------------------------------------------------------------
__global__ __launch_bounds__(256) void main_kernel(const float* __restrict__ in,
                                                   float* __restrict__ out) {
    __shared__ __align__(16) float srk2[NCH * 20];
    __shared__ float tile[64 * 64];

    int tid = threadIdx.x;
    for (int i = tid; i < NCH * 20; i += 256) srk2[i] = g_rk2[i];
    float sq = g_sqx;

    int h    = blockIdx.y;
    int wblk = blockIdx.x * 64;
    int w4   = tid & 15;
    int cbg  = tid >> 4;
    int cb   = cbg * 4;
    int wloc = w4 * 4;

    // column-validity masks (x sq), packed per element-pair
    float cm0[4], cm2[4];
#pragma unroll
    for (int j = 0; j < 4; j++) {
        int gw = wblk + wloc + j;
        cm0[j] = (gw != 511) ? sq : 0.f;
        cm2[j] = (gw != 0)   ? sq : 0.f;
    }
    ull CW[3][2];
#pragma unroll
    for (int p = 0; p < 2; p++) {
        CW[0][p] = pk2(cm0[2 * p], cm0[2 * p + 1]);
        CW[1][p] = pk2(sq, sq);
        CW[2][p] = pk2(cm2[2 * p], cm2[2 * p + 1]);
    }
    ull MSK[9][2];
    if (h != 0 && h != 511) {
#pragma unroll
        for (int tt = 0; tt < 9; tt++) {
            MSK[tt][0] = CW[tt % 3][0];
            MSK[tt][1] = CW[tt % 3][1];
        }
    } else {
        float rmh[3] = { (h != 511) ? 1.f : 0.f, 1.f, (h != 0) ? 1.f : 0.f };
#pragma unroll
        for (int tt = 0; tt < 9; tt++) {
            ull rh = pk2(rmh[tt / 3], rmh[tt / 3]);
            MSK[tt][0] = f2mul(CW[tt % 3][0], rh);
            MSK[tt][1] = f2mul(CW[tt % 3][1], rh);
        }
    }
    const ull MM2 = pk2(RMAGIC, RMAGIC);
    const ull NM2 = pk2(-RMAGIC, -RMAGIC);
    __syncthreads();

    float a[4][4];
    size_t base = (size_t)h * 512 + wblk + wloc;
#pragma unroll
    for (int i = 0; i < 4; i++) {
        int c = cb + i;
        // duplicated scale pairs, loaded pre-packed
        const double2* kt = reinterpret_cast<const double2*>(&srk2[c * 20]);
        double2 A = kt[0], B = kt[1], C2 = kt[2], D = kt[3];
        double   E = *reinterpret_cast<const double*>(&srk2[c * 20 + 16]);
        ull KK[9] = { __double_as_longlong(A.x), __double_as_longlong(A.y),
                      __double_as_longlong(B.x), __double_as_longlong(B.y),
                      __double_as_longlong(C2.x), __double_as_longlong(C2.y),
                      __double_as_longlong(D.x), __double_as_longlong(D.y),
                      __double_as_longlong(E) };
        ulonglong2 X2 = *reinterpret_cast<const ulonglong2*>(in + (size_t)c * HWX + base);
#pragma unroll
        for (int p = 0; p < 2; p++) {
            ull X = p ? X2.y : X2.x;
            ull acc = f2mul(f2add(f2fma(X, KK[0], MM2), NM2), MSK[0][p]);
#pragma unroll
            for (int tt = 1; tt < 9; tt++) {
                ull R = f2add(f2fma(X, KK[tt], MM2), NM2);
                acc = f2fma(R, MSK[tt][p], acc);
            }
            upk2(acc, a[i][2 * p], a[i][2 * p + 1]);
        }
    }

    // register transpose -> smem; XOR swizzle conflict-free both phases
#pragma unroll
    for (int j = 0; j < 4; j++) {
        int row = wloc + j;
        int col = (cbg ^ w4) << 2;
        *reinterpret_cast<float4*>(&tile[row * 64 + col]) =
            make_float4(a[0][j], a[1][j], a[2][j], a[3][j]);
    }
    __syncthreads();

    int cg = tid & 15;
    int wr = tid >> 4;
    float* ob = out + 36864 + ((size_t)h * 512 + wblk) * 64;
#pragma unroll
    for (int jj = 0; jj < 4; jj++) {
        int w = wr + 16 * jj;
        float4 t4 = *reinterpret_cast<const float4*>(
            &tile[w * 64 + ((cg ^ (w >> 2)) << 2)]);
        *reinterpret_cast<float4*>(&ob[(size_t)w * 64 + cg * 4]) = t4;
    }
}

// ---------------------------------------------------------------------------
extern "C" void kernel_launch(void* const* d_in, const int* in_sizes, int n_in,
                              void* d_out, int out_size) {
    const float* in;
    const float* w;
    if (in_sizes[0] == 64 * 512 * 512) { in = (const float*)d_in[0]; w = (const float*)d_in[1]; }
    else                               { in = (const float*)d_in[1]; w = (const float*)d_in[0]; }
    float* out = (float*)d_out;

    dim3 g1(9, 64);
    actmax_kernel<<<g1, 256>>>(in, w);
    scale_kernel<<<1, 576>>>();
    wq_kernel<<<64, 576>>>(w, out);
    dim3 g3(8, 512);
    main_kernel<<<g3, 256>>>(in, out);
}